// round 2
// baseline (speedup 1.0000x reference)
#include <cuda_runtime.h>
#include <cuda_bf16.h>

#define NB 4096
#define NS 256
#define ND 32

// scratch for pooled features [4096][128]
__device__ float g_pooled[NB * 128];

// histogram layout in smem: job[11] @0, rep[34] @11, place[19] @45, add[31] @64  -> 95 ints
#define H_JOB 0
#define H_REP 11
#define H_PLACE 45
#define H_ADD 64
#define H_TOT 95

__global__ __launch_bounds__(256, 4)
void pool_kernel(const float* __restrict__ cont_p, const float* __restrict__ cont_c,
                 const int* __restrict__ cat_p, const int* __restrict__ cat_c,
                 const int* __restrict__ lengths,
                 const float* __restrict__ w_p1, const float* __restrict__ b_p1,
                 const float* __restrict__ w_p2, const float* __restrict__ b_p2,
                 const float* __restrict__ w_c1, const float* __restrict__ b_c1,
                 const float* __restrict__ w_c2, const float* __restrict__ b_c2,
                 const float* __restrict__ eg, const float* __restrict__ ek,
                 const float* __restrict__ epr, const float* __restrict__ ejob,
                 const float* __restrict__ erep, const float* __restrict__ epl,
                 const float* __restrict__ eadd)
{
    const int b = blockIdx.x;
    const int tid = threadIdx.x;
    const int lane = tid & 31;
    const int w = tid >> 5;

    __shared__ int s_bin[3];        // index-sums for gender/korean/primary (vocab 2)
    __shared__ int s_hist[H_TOT];   // histograms for job/rep/place/add
    __shared__ float s_red[2][8][32];
    __shared__ float s_apsum[32];
    __shared__ float s_acsum[32];

    if (tid < 3) s_bin[tid] = 0;
    if (tid < H_TOT) s_hist[tid] = 0;
    __syncthreads();

    const int len = lengths[b];

    // per-lane (lane = output dim) weights for the first linear layers
    const float wa0 = w_p1[lane], wa1 = w_p1[32 + lane], wa2 = w_p1[64 + lane], ba = b_p1[lane];
    const float wb0 = w_c1[lane], wb1 = w_c1[32 + lane], bb = b_c1[lane];

    float ap_acc = 0.f, ac_acc = 0.f;
    int binsum = 0;

    const int rowbase = b * NS;
    for (int t = w; t < len; t += 8) {
        const int r = rowbase + t;
        float cp = 0.f, cc = 0.f;
        int vp = 0, vc = 0;
        if (lane < 3) cp = cont_p[r * 3 + lane];
        if (lane < 2) cc = cont_c[r * 2 + lane];
        if (lane < 5) vp = cat_p[r * 5 + lane];
        if (lane < 2) vc = cat_c[r * 2 + lane];

        float x0 = __shfl_sync(0xffffffffu, cp, 0);
        float x1 = __shfl_sync(0xffffffffu, cp, 1);
        float x2 = __shfl_sync(0xffffffffu, cp, 2);
        float y0 = __shfl_sync(0xffffffffu, cc, 0);
        float y1 = __shfl_sync(0xffffffffu, cc, 1);

        if (lane < 3) binsum += vp;                       // binary vocab -> count of ones
        if (lane == 3) atomicAdd(&s_hist[H_JOB + vp], 1);
        if (lane == 4) atomicAdd(&s_hist[H_REP + vp], 1);
        if (lane == 0) atomicAdd(&s_hist[H_PLACE + vc], 1);
        if (lane == 1) atomicAdd(&s_hist[H_ADD + vc], 1);

        float ap = fmaf(x2, wa2, fmaf(x1, wa1, fmaf(x0, wa0, ba)));
        ap_acc += fmaxf(ap, 0.f);
        float ac = fmaf(y1, wb1, fmaf(y0, wb0, bb));
        ac_acc += fmaxf(ac, 0.f);
    }

    if (lane < 3) atomicAdd(&s_bin[lane], binsum);
    s_red[0][w][lane] = ap_acc;
    s_red[1][w][lane] = ac_acc;
    __syncthreads();

    if (tid < 32) {
        float s = 0.f;
        #pragma unroll
        for (int i = 0; i < 8; i++) s += s_red[0][i][tid];
        s_apsum[tid] = s;
    } else if (tid < 64) {
        const int l = tid - 32;
        float s = 0.f;
        #pragma unroll
        for (int i = 0; i < 8; i++) s += s_red[1][i][l];
        s_acsum[l] = s;
    }
    __syncthreads();

    // tail: 128 threads compute pooled[128] for this batch
    if (tid < 128) {
        const float flen = (float)len;
        const float inv_len = 1.0f / flen;
        float pooled;
        if (tid < 32) {
            const int dd = tid;
            const float n1g = (float)s_bin[0];
            const float n1k = (float)s_bin[1];
            const float n1p = (float)s_bin[2];
            float e = (flen - n1g) * eg[dd]  + n1g * eg[32 + dd]
                    + (flen - n1k) * ek[dd]  + n1k * ek[32 + dd]
                    + (flen - n1p) * epr[dd] + n1p * epr[32 + dd];
            #pragma unroll
            for (int v = 0; v < 11; v++) e = fmaf((float)s_hist[H_JOB + v], ejob[v * 32 + dd], e);
            #pragma unroll
            for (int v = 0; v < 34; v++) e = fmaf((float)s_hist[H_REP + v], erep[v * 32 + dd], e);
            pooled = e * (inv_len * 0.2f);
        } else if (tid < 64) {
            const int dd = tid - 32;
            float e = 0.f;
            #pragma unroll
            for (int v = 0; v < 19; v++) e = fmaf((float)s_hist[H_PLACE + v], epl[v * 32 + dd], e);
            #pragma unroll
            for (int v = 0; v < 31; v++) e = fmaf((float)s_hist[H_ADD + v], eadd[v * 32 + dd], e);
            pooled = e * (inv_len * 0.5f);
        } else if (tid < 96) {
            const int dd = tid - 64;
            float s = 0.f;
            #pragma unroll
            for (int k = 0; k < 32; k++) s = fmaf(s_apsum[k], w_p2[k * 32 + dd], s);
            pooled = fmaf(s, inv_len, b_p2[dd]);
        } else {
            const int dd = tid - 96;
            float s = 0.f;
            #pragma unroll
            for (int k = 0; k < 32; k++) s = fmaf(s_acsum[k], w_c2[k * 32 + dd], s);
            pooled = fmaf(s, inv_len, b_c2[dd]);
        }
        g_pooled[b * 128 + tid] = pooled;
    }
}

// head: pooled[4096][128] @ w_fc1[128][64] + b -> relu -> @ w_fc2[64][2] + b -> relu
__global__ __launch_bounds__(256, 2)
void head_kernel(const float* __restrict__ w_fc1, const float* __restrict__ b_fc1,
                 const float* __restrict__ w_fc2, const float* __restrict__ b_fc2,
                 float* __restrict__ out)
{
    __shared__ float s_w1[128 * 64];   // 32 KB
    __shared__ float s_b1[64];
    __shared__ float s_w2[128];
    __shared__ float s_b2[2];
    __shared__ float s_p[4][128];
    __shared__ float s_h1[4][64];

    const int tid = threadIdx.x;
    for (int i = tid; i < 128 * 64; i += 256) s_w1[i] = w_fc1[i];
    if (tid < 64) s_b1[tid] = b_fc1[tid];
    if (tid < 128) s_w2[tid] = w_fc2[tid];
    if (tid < 2) s_b2[tid] = b_fc2[tid];
    __syncthreads();

    const int j = tid & 63;
    const int bb = tid >> 6;   // 0..3 batches in flight

    for (int it = 0; it < 16; it++) {
        const int bgrp = blockIdx.x * 64 + it * 4;   // first batch of this group of 4
        for (int i = tid; i < 512; i += 256)
            s_p[i >> 7][i & 127] = g_pooled[bgrp * 128 + i];
        __syncthreads();

        float s = s_b1[j];
        #pragma unroll
        for (int d = 0; d < 128; d++) s = fmaf(s_p[bb][d], s_w1[d * 64 + j], s);
        s_h1[bb][j] = fmaxf(s, 0.f);
        __syncthreads();

        if (tid < 8) {
            const int o = tid & 1;
            const int bl = tid >> 1;
            float acc = s_b2[o];
            #pragma unroll
            for (int jj = 0; jj < 64; jj++) acc = fmaf(s_h1[bl][jj], s_w2[jj * 2 + o], acc);
            out[(bgrp + bl) * 2 + o] = fmaxf(acc, 0.f);
        }
        __syncthreads();
    }
}

extern "C" void kernel_launch(void* const* d_in, const int* in_sizes, int n_in,
                              void* d_out, int out_size)
{
    const float* cont_p = (const float*)d_in[0];
    const float* cont_c = (const float*)d_in[1];
    const int*   cat_p  = (const int*)d_in[2];
    const int*   cat_c  = (const int*)d_in[3];
    const int*   lengths= (const int*)d_in[4];
    const float* w_p1   = (const float*)d_in[5];
    const float* b_p1   = (const float*)d_in[6];
    const float* w_p2   = (const float*)d_in[7];
    const float* b_p2   = (const float*)d_in[8];
    const float* w_c1   = (const float*)d_in[9];
    const float* b_c1   = (const float*)d_in[10];
    const float* w_c2   = (const float*)d_in[11];
    const float* b_c2   = (const float*)d_in[12];
    const float* eg     = (const float*)d_in[13];
    const float* ek     = (const float*)d_in[14];
    const float* epr    = (const float*)d_in[15];
    const float* ejob   = (const float*)d_in[16];
    const float* erep   = (const float*)d_in[17];
    const float* epl    = (const float*)d_in[18];
    const float* eadd   = (const float*)d_in[19];
    const float* w_fc1  = (const float*)d_in[20];
    const float* b_fc1  = (const float*)d_in[21];
    const float* w_fc2  = (const float*)d_in[22];
    const float* b_fc2  = (const float*)d_in[23];
    float* out = (float*)d_out;

    pool_kernel<<<NB, 256>>>(cont_p, cont_c, cat_p, cat_c, lengths,
                             w_p1, b_p1, w_p2, b_p2, w_c1, b_c1, w_c2, b_c2,
                             eg, ek, epr, ejob, erep, epl, eadd);
    head_kernel<<<NB / 64, 256>>>(w_fc1, b_fc1, w_fc2, b_fc2, out);
}

// round 3
// speedup vs baseline: 4.0281x; 4.0281x over previous
#include <cuda_runtime.h>
#include <cuda_bf16.h>

#define NB 4096
#define NS 256
#define ND 32

// scratch for pooled features [4096][128]
__device__ float g_pooled[NB * 128];

// histogram layout in smem: job[11] @0, rep[34] @11, place[19] @45, add[31] @64 -> 95 ints
#define H_JOB 0
#define H_REP 11
#define H_PLACE 45
#define H_ADD 64
#define H_TOT 95

__global__ __launch_bounds__(256)
void pool_kernel(const float* __restrict__ cont_p, const float* __restrict__ cont_c,
                 const int* __restrict__ cat_p, const int* __restrict__ cat_c,
                 const int* __restrict__ lengths,
                 const float* __restrict__ w_p1, const float* __restrict__ b_p1,
                 const float* __restrict__ w_p2, const float* __restrict__ b_p2,
                 const float* __restrict__ w_c1, const float* __restrict__ b_c1,
                 const float* __restrict__ w_c2, const float* __restrict__ b_c2,
                 const float* __restrict__ eg, const float* __restrict__ ek,
                 const float* __restrict__ epr, const float* __restrict__ ejob,
                 const float* __restrict__ erep, const float* __restrict__ epl,
                 const float* __restrict__ eadd)
{
    const int b = blockIdx.x;
    const int tid = threadIdx.x;
    const int lane = tid & 31;
    const int w = tid >> 5;

    __shared__ float4 s_t4[NS];          // {x0,x1,x2,y0} per token
    __shared__ float s_y1[NS];
    __shared__ int s_hist[H_TOT];
    __shared__ unsigned s_binpack;       // gender | korean<<10 | primary<<20
    __shared__ float s_red[2][8][32];
    __shared__ float s_apsum[32];
    __shared__ float s_acsum[32];

    if (tid < H_TOT) s_hist[tid] = 0;
    if (tid == 0) s_binpack = 0u;
    __syncthreads();

    const int len = lengths[b];
    const int rowbase = b * NS;

    // ---- Phase A: thread-per-token coalesced staging + warp-aggregated histograms ----
    {
        const int t = tid;
        const unsigned act = __ballot_sync(0xffffffffu, t < len);
        if (t < len) {
            const int r = rowbase + t;
            const float x0 = cont_p[r * 3 + 0];
            const float x1 = cont_p[r * 3 + 1];
            const float x2 = cont_p[r * 3 + 2];
            const float y0 = cont_c[r * 2 + 0];
            const float y1 = cont_c[r * 2 + 1];
            s_t4[t] = make_float4(x0, x1, x2, y0);
            s_y1[t] = y1;

            const int v0 = cat_p[r * 5 + 0];
            const int v1 = cat_p[r * 5 + 1];
            const int v2 = cat_p[r * 5 + 2];
            const int v3 = cat_p[r * 5 + 3];
            const int v4 = cat_p[r * 5 + 4];
            const int c0 = cat_c[r * 2 + 0];
            const int c1 = cat_c[r * 2 + 1];

            // binary vocab columns: packed warp reduce (warp sums <= 32 per field)
            const unsigned packed = (unsigned)v0 | ((unsigned)v1 << 10) | ((unsigned)v2 << 20);
            const unsigned wsum = __reduce_add_sync(act, packed);
            if (lane == 0) atomicAdd(&s_binpack, wsum);   // lane0 always active (contiguous)

            // warp-aggregated histogram adds
            {
                unsigned mm = __match_any_sync(act, v3);
                if (lane == __ffs(mm) - 1) atomicAdd(&s_hist[H_JOB + v3], __popc(mm));
            }
            {
                unsigned mm = __match_any_sync(act, v4);
                if (lane == __ffs(mm) - 1) atomicAdd(&s_hist[H_REP + v4], __popc(mm));
            }
            {
                unsigned mm = __match_any_sync(act, c0);
                if (lane == __ffs(mm) - 1) atomicAdd(&s_hist[H_PLACE + c0], __popc(mm));
            }
            {
                unsigned mm = __match_any_sync(act, c1);
                if (lane == __ffs(mm) - 1) atomicAdd(&s_hist[H_ADD + c1], __popc(mm));
            }
        }
    }
    __syncthreads();

    // ---- Phase B: lane = output dim, 8 warps split tokens; data via LDS broadcast ----
    const float wa0 = w_p1[lane], wa1 = w_p1[32 + lane], wa2 = w_p1[64 + lane], ba = b_p1[lane];
    const float wb0 = w_c1[lane], wb1 = w_c1[32 + lane], bb = b_c1[lane];

    float ap_acc = 0.f, ac_acc = 0.f;
    #pragma unroll 4
    for (int t = w; t < len; t += 8) {
        const float4 v = s_t4[t];
        const float y1 = s_y1[t];
        float ap = fmaf(v.z, wa2, fmaf(v.y, wa1, fmaf(v.x, wa0, ba)));
        ap_acc += fmaxf(ap, 0.f);
        float ac = fmaf(y1, wb1, fmaf(v.w, wb0, bb));
        ac_acc += fmaxf(ac, 0.f);
    }

    s_red[0][w][lane] = ap_acc;
    s_red[1][w][lane] = ac_acc;
    __syncthreads();

    if (tid < 32) {
        float s = 0.f;
        #pragma unroll
        for (int i = 0; i < 8; i++) s += s_red[0][i][tid];
        s_apsum[tid] = s;
    } else if (tid < 64) {
        const int l = tid - 32;
        float s = 0.f;
        #pragma unroll
        for (int i = 0; i < 8; i++) s += s_red[1][i][l];
        s_acsum[l] = s;
    }
    __syncthreads();

    // ---- tail: 128 threads compute pooled[128] for this batch ----
    if (tid < 128) {
        const float flen = (float)len;
        const float inv_len = 1.0f / flen;
        float pooled;
        if (tid < 32) {
            const int dd = tid;
            const unsigned bp = s_binpack;
            const float n1g = (float)(bp & 1023u);
            const float n1k = (float)((bp >> 10) & 1023u);
            const float n1p = (float)((bp >> 20) & 1023u);
            float e = (flen - n1g) * eg[dd]  + n1g * eg[32 + dd]
                    + (flen - n1k) * ek[dd]  + n1k * ek[32 + dd]
                    + (flen - n1p) * epr[dd] + n1p * epr[32 + dd];
            #pragma unroll
            for (int v = 0; v < 11; v++) e = fmaf((float)s_hist[H_JOB + v], ejob[v * 32 + dd], e);
            #pragma unroll
            for (int v = 0; v < 34; v++) e = fmaf((float)s_hist[H_REP + v], erep[v * 32 + dd], e);
            pooled = e * (inv_len * 0.2f);
        } else if (tid < 64) {
            const int dd = tid - 32;
            float e = 0.f;
            #pragma unroll
            for (int v = 0; v < 19; v++) e = fmaf((float)s_hist[H_PLACE + v], epl[v * 32 + dd], e);
            #pragma unroll
            for (int v = 0; v < 31; v++) e = fmaf((float)s_hist[H_ADD + v], eadd[v * 32 + dd], e);
            pooled = e * (inv_len * 0.5f);
        } else if (tid < 96) {
            const int dd = tid - 64;
            float s = 0.f;
            #pragma unroll
            for (int k = 0; k < 32; k++) s = fmaf(s_apsum[k], w_p2[k * 32 + dd], s);
            pooled = fmaf(s, inv_len, b_p2[dd]);
        } else {
            const int dd = tid - 96;
            float s = 0.f;
            #pragma unroll
            for (int k = 0; k < 32; k++) s = fmaf(s_acsum[k], w_c2[k * 32 + dd], s);
            pooled = fmaf(s, inv_len, b_c2[dd]);
        }
        g_pooled[b * 128 + tid] = pooled;
    }
}

// head: pooled[4096][128] @ w_fc1[128][64] + b -> relu -> @ w_fc2[64][2] + b -> relu
// grid=512, block=512, 8 batches per CTA, single pass
__global__ __launch_bounds__(512)
void head_kernel(const float* __restrict__ w_fc1, const float* __restrict__ b_fc1,
                 const float* __restrict__ w_fc2, const float* __restrict__ b_fc2,
                 float* __restrict__ out)
{
    __shared__ float s_w1[128 * 64];   // 32 KB
    __shared__ float s_b1[64];
    __shared__ float s_w2[128];
    __shared__ float s_b2[2];
    __shared__ float s_p[8][128];
    __shared__ float s_h1[8][64];

    const int tid = threadIdx.x;
    for (int i = tid; i < 128 * 64; i += 512) s_w1[i] = w_fc1[i];
    if (tid < 64) s_b1[tid] = b_fc1[tid];
    if (tid < 128) s_w2[tid] = w_fc2[tid];
    if (tid < 2) s_b2[tid] = b_fc2[tid];

    const int bgrp = blockIdx.x * 8;
    for (int i = tid; i < 1024; i += 512)
        s_p[i >> 7][i & 127] = g_pooled[bgrp * 128 + i];
    __syncthreads();

    const int j = tid & 63;
    const int bb = tid >> 6;   // 0..7 batches in flight

    float s = s_b1[j];
    #pragma unroll
    for (int d = 0; d < 128; d++) s = fmaf(s_p[bb][d], s_w1[d * 64 + j], s);
    s_h1[bb][j] = fmaxf(s, 0.f);
    __syncthreads();

    if (tid < 16) {
        const int o = tid & 1;
        const int bl = tid >> 1;
        float acc = s_b2[o];
        #pragma unroll
        for (int jj = 0; jj < 64; jj++) acc = fmaf(s_h1[bl][jj], s_w2[jj * 2 + o], acc);
        out[(bgrp + bl) * 2 + o] = fmaxf(acc, 0.f);
    }
}

extern "C" void kernel_launch(void* const* d_in, const int* in_sizes, int n_in,
                              void* d_out, int out_size)
{
    const float* cont_p = (const float*)d_in[0];
    const float* cont_c = (const float*)d_in[1];
    const int*   cat_p  = (const int*)d_in[2];
    const int*   cat_c  = (const int*)d_in[3];
    const int*   lengths= (const int*)d_in[4];
    const float* w_p1   = (const float*)d_in[5];
    const float* b_p1   = (const float*)d_in[6];
    const float* w_p2   = (const float*)d_in[7];
    const float* b_p2   = (const float*)d_in[8];
    const float* w_c1   = (const float*)d_in[9];
    const float* b_c1   = (const float*)d_in[10];
    const float* w_c2   = (const float*)d_in[11];
    const float* b_c2   = (const float*)d_in[12];
    const float* eg     = (const float*)d_in[13];
    const float* ek     = (const float*)d_in[14];
    const float* epr    = (const float*)d_in[15];
    const float* ejob   = (const float*)d_in[16];
    const float* erep   = (const float*)d_in[17];
    const float* epl    = (const float*)d_in[18];
    const float* eadd   = (const float*)d_in[19];
    const float* w_fc1  = (const float*)d_in[20];
    const float* b_fc1  = (const float*)d_in[21];
    const float* w_fc2  = (const float*)d_in[22];
    const float* b_fc2  = (const float*)d_in[23];
    float* out = (float*)d_out;

    pool_kernel<<<NB, 256>>>(cont_p, cont_c, cat_p, cat_c, lengths,
                             w_p1, b_p1, w_p2, b_p2, w_c1, b_c1, w_c2, b_c2,
                             eg, ek, epr, ejob, erep, epl, eadd);
    head_kernel<<<512, 512>>>(w_fc1, b_fc1, w_fc2, b_fc2, out);
}

// round 4
// speedup vs baseline: 4.8585x; 1.2062x over previous
#include <cuda_runtime.h>
#include <cuda_bf16.h>

#define NB 4096
#define NS 256
#define ND 32

// scratch for pooled features [4096][128]
__device__ float g_pooled[NB * 128];

// histogram layout in smem: job[11] @0, rep[34] @11, place[19] @45, add[31] @64 -> 95 ints
#define H_JOB 0
#define H_REP 11
#define H_PLACE 45
#define H_ADD 64
#define H_TOT 95

__global__ __launch_bounds__(256)
void pool_kernel(const float* __restrict__ cont_p, const float* __restrict__ cont_c,
                 const int* __restrict__ cat_p, const int* __restrict__ cat_c,
                 const int* __restrict__ lengths,
                 const float* __restrict__ w_p1, const float* __restrict__ b_p1,
                 const float* __restrict__ w_p2, const float* __restrict__ b_p2,
                 const float* __restrict__ w_c1, const float* __restrict__ b_c1,
                 const float* __restrict__ w_c2, const float* __restrict__ b_c2,
                 const float* __restrict__ eg, const float* __restrict__ ek,
                 const float* __restrict__ epr, const float* __restrict__ ejob,
                 const float* __restrict__ erep, const float* __restrict__ epl,
                 const float* __restrict__ eadd)
{
    const int b = blockIdx.x;
    const int tid = threadIdx.x;
    const int lane = tid & 31;
    const int w = tid >> 5;

    // raw staged inputs for this batch
    __shared__ float4 s_cp4[192];   // cont_p: up to 768 floats
    __shared__ float4 s_cc4[128];   // cont_c: up to 512 floats
    __shared__ int4   s_vp4[320];   // cat_p:  up to 1280 ints
    __shared__ int4   s_vc4[128];   // cat_c:  up to 512 ints
    __shared__ int s_hist[H_TOT];
    __shared__ unsigned s_binpack;  // gender | korean<<10 | primary<<20
    __shared__ float s_red[2][8][32];
    __shared__ float s_apsum[32];
    __shared__ float s_acsum[32];

    if (tid < H_TOT) s_hist[tid] = 0;
    if (tid == 0) s_binpack = 0u;

    const int len = lengths[b];

    // ---- Phase A: exact-length vectorized staging (all coalesced 16B loads) ----
    {
        const int ncp = (3 * len + 3) >> 2;   // <= 192
        const int ncc = (2 * len + 3) >> 2;   // <= 128
        const int nvp = (5 * len + 3) >> 2;   // <= 320
        const int nvc = (2 * len + 3) >> 2;   // <= 128

        const float4* gcp = (const float4*)(cont_p + b * (NS * 3));
        const float4* gcc = (const float4*)(cont_c + b * (NS * 2));
        const int4*   gvp = (const int4*)(cat_p + b * (NS * 5));
        const int4*   gvc = (const int4*)(cat_c + b * (NS * 2));

        if (tid < ncp) s_cp4[tid] = gcp[tid];
        if (tid < ncc) s_cc4[tid] = gcc[tid];
        if (tid < nvp) s_vp4[tid] = gvp[tid];
        if (tid + 256 < nvp) s_vp4[tid + 256] = gvp[tid + 256];
        if (tid < nvc) s_vc4[tid] = gvc[tid];
    }
    __syncthreads();

    // ---- Phase A2: thread-per-token histograms from smem ----
    {
        const int t = tid;
        const unsigned act = __ballot_sync(0xffffffffu, t < len);
        if (t < len) {
            const int* sp = (const int*)s_vp4;
            const int* sc = (const int*)s_vc4;
            const int v0 = sp[t * 5 + 0];
            const int v1 = sp[t * 5 + 1];
            const int v2 = sp[t * 5 + 2];
            const int v3 = sp[t * 5 + 3];
            const int v4 = sp[t * 5 + 4];
            const int c0 = sc[t * 2 + 0];
            const int c1 = sc[t * 2 + 1];

            const unsigned packed = (unsigned)v0 | ((unsigned)v1 << 10) | ((unsigned)v2 << 20);
            const unsigned wsum = __reduce_add_sync(act, packed);
            if (lane == 0) atomicAdd(&s_binpack, wsum);

            {
                unsigned mm = __match_any_sync(act, v3);
                if (lane == __ffs(mm) - 1) atomicAdd(&s_hist[H_JOB + v3], __popc(mm));
            }
            {
                unsigned mm = __match_any_sync(act, v4);
                if (lane == __ffs(mm) - 1) atomicAdd(&s_hist[H_REP + v4], __popc(mm));
            }
            {
                unsigned mm = __match_any_sync(act, c0);
                if (lane == __ffs(mm) - 1) atomicAdd(&s_hist[H_PLACE + c0], __popc(mm));
            }
            {
                unsigned mm = __match_any_sync(act, c1);
                if (lane == __ffs(mm) - 1) atomicAdd(&s_hist[H_ADD + c1], __popc(mm));
            }
        }
    }

    // ---- Phase B: lane = output dim, 8 warps split tokens; broadcast LDS ----
    const float wa0 = w_p1[lane], wa1 = w_p1[32 + lane], wa2 = w_p1[64 + lane], ba = b_p1[lane];
    const float wb0 = w_c1[lane], wb1 = w_c1[32 + lane], bb = b_c1[lane];

    const float* scp = (const float*)s_cp4;
    const float* scc = (const float*)s_cc4;

    float ap_acc = 0.f, ac_acc = 0.f;
    #pragma unroll 4
    for (int t = w; t < len; t += 8) {
        const float x0 = scp[t * 3 + 0];
        const float x1 = scp[t * 3 + 1];
        const float x2 = scp[t * 3 + 2];
        const float y0 = scc[t * 2 + 0];
        const float y1 = scc[t * 2 + 1];
        float ap = fmaf(x2, wa2, fmaf(x1, wa1, fmaf(x0, wa0, ba)));
        ap_acc += fmaxf(ap, 0.f);
        float ac = fmaf(y1, wb1, fmaf(y0, wb0, bb));
        ac_acc += fmaxf(ac, 0.f);
    }

    s_red[0][w][lane] = ap_acc;
    s_red[1][w][lane] = ac_acc;
    __syncthreads();

    if (tid < 32) {
        float s = 0.f;
        #pragma unroll
        for (int i = 0; i < 8; i++) s += s_red[0][i][tid];
        s_apsum[tid] = s;
    } else if (tid < 64) {
        const int l = tid - 32;
        float s = 0.f;
        #pragma unroll
        for (int i = 0; i < 8; i++) s += s_red[1][i][l];
        s_acsum[l] = s;
    }
    __syncthreads();

    // ---- tail: 128 threads compute pooled[128] for this batch ----
    if (tid < 128) {
        const float flen = (float)len;
        const float inv_len = 1.0f / flen;
        float pooled;
        if (tid < 32) {
            const int dd = tid;
            const unsigned bp = s_binpack;
            const float n1g = (float)(bp & 1023u);
            const float n1k = (float)((bp >> 10) & 1023u);
            const float n1p = (float)((bp >> 20) & 1023u);
            float e = (flen - n1g) * eg[dd]  + n1g * eg[32 + dd]
                    + (flen - n1k) * ek[dd]  + n1k * ek[32 + dd]
                    + (flen - n1p) * epr[dd] + n1p * epr[32 + dd];
            #pragma unroll
            for (int v = 0; v < 11; v++) e = fmaf((float)s_hist[H_JOB + v], ejob[v * 32 + dd], e);
            #pragma unroll
            for (int v = 0; v < 34; v++) e = fmaf((float)s_hist[H_REP + v], erep[v * 32 + dd], e);
            pooled = e * (inv_len * 0.2f);
        } else if (tid < 64) {
            const int dd = tid - 32;
            float e = 0.f;
            #pragma unroll
            for (int v = 0; v < 19; v++) e = fmaf((float)s_hist[H_PLACE + v], epl[v * 32 + dd], e);
            #pragma unroll
            for (int v = 0; v < 31; v++) e = fmaf((float)s_hist[H_ADD + v], eadd[v * 32 + dd], e);
            pooled = e * (inv_len * 0.5f);
        } else if (tid < 96) {
            const int dd = tid - 64;
            float s = 0.f;
            #pragma unroll
            for (int k = 0; k < 32; k++) s = fmaf(s_apsum[k], w_p2[k * 32 + dd], s);
            pooled = fmaf(s, inv_len, b_p2[dd]);
        } else {
            const int dd = tid - 96;
            float s = 0.f;
            #pragma unroll
            for (int k = 0; k < 32; k++) s = fmaf(s_acsum[k], w_c2[k * 32 + dd], s);
            pooled = fmaf(s, inv_len, b_c2[dd]);
        }
        g_pooled[b * 128 + tid] = pooled;
    }
}

// head: register-tiled GEMM. CTA = 32 batches x 64 cols, thread tile = 4 batches x 2 cols.
// grid = 128, block = 256.
__global__ __launch_bounds__(256)
void head_kernel(const float* __restrict__ w_fc1, const float* __restrict__ b_fc1,
                 const float* __restrict__ w_fc2, const float* __restrict__ b_fc2,
                 float* __restrict__ out)
{
    __shared__ float s_w1[128 * 64];   // 32 KB
    __shared__ float s_p[32][128];     // 16 KB
    __shared__ float s_h1[32][64];     // 8 KB

    const int tid = threadIdx.x;
    const int bgrp = blockIdx.x * 32;

    // stage w1 (2048 float4) and p tile (1024 float4)
    {
        const float4* gw = (const float4*)w_fc1;
        float4* sw = (float4*)s_w1;
        #pragma unroll
        for (int i = 0; i < 8; i++) sw[tid + 256 * i] = gw[tid + 256 * i];
        const float4* gp = (const float4*)(g_pooled + bgrp * 128);
        float4* sp = (float4*)&s_p[0][0];
        #pragma unroll
        for (int i = 0; i < 4; i++) sp[tid + 256 * i] = gp[tid + 256 * i];
    }
    __syncthreads();

    const int jj = tid & 31;    // col pair: j = 2*jj, 2*jj+1
    const int bq = tid >> 5;    // batch quad: batches 4*bq .. 4*bq+3

    const float bias0 = b_fc1[2 * jj];
    const float bias1 = b_fc1[2 * jj + 1];
    float acc[4][2];
    #pragma unroll
    for (int i = 0; i < 4; i++) { acc[i][0] = bias0; acc[i][1] = bias1; }

    #pragma unroll 4
    for (int d0 = 0; d0 < 128; d0 += 4) {
        float4 pv[4];
        #pragma unroll
        for (int i = 0; i < 4; i++) pv[i] = *(const float4*)&s_p[4 * bq + i][d0];
        #pragma unroll
        for (int k = 0; k < 4; k++) {
            const float2 wv = *(const float2*)&s_w1[(d0 + k) * 64 + 2 * jj];
            const float pk0 = (&pv[0].x)[k];
            const float pk1 = (&pv[1].x)[k];
            const float pk2 = (&pv[2].x)[k];
            const float pk3 = (&pv[3].x)[k];
            acc[0][0] = fmaf(pk0, wv.x, acc[0][0]); acc[0][1] = fmaf(pk0, wv.y, acc[0][1]);
            acc[1][0] = fmaf(pk1, wv.x, acc[1][0]); acc[1][1] = fmaf(pk1, wv.y, acc[1][1]);
            acc[2][0] = fmaf(pk2, wv.x, acc[2][0]); acc[2][1] = fmaf(pk2, wv.y, acc[2][1]);
            acc[3][0] = fmaf(pk3, wv.x, acc[3][0]); acc[3][1] = fmaf(pk3, wv.y, acc[3][1]);
        }
    }

    #pragma unroll
    for (int i = 0; i < 4; i++) {
        s_h1[4 * bq + i][2 * jj]     = fmaxf(acc[i][0], 0.f);
        s_h1[4 * bq + i][2 * jj + 1] = fmaxf(acc[i][1], 0.f);
    }
    __syncthreads();

    // fc2: 64 threads, one (batch, output) pair each
    if (tid < 64) {
        const int o = tid & 1;
        const int bl = tid >> 1;
        float a0 = b_fc2[o], a1 = 0.f, a2 = 0.f, a3 = 0.f;
        #pragma unroll
        for (int j = 0; j < 64; j += 4) {
            a0 = fmaf(s_h1[bl][j],     w_fc2[j * 2 + o],       a0);
            a1 = fmaf(s_h1[bl][j + 1], w_fc2[(j + 1) * 2 + o], a1);
            a2 = fmaf(s_h1[bl][j + 2], w_fc2[(j + 2) * 2 + o], a2);
            a3 = fmaf(s_h1[bl][j + 3], w_fc2[(j + 3) * 2 + o], a3);
        }
        out[(bgrp + bl) * 2 + o] = fmaxf((a0 + a1) + (a2 + a3), 0.f);
    }
}

extern "C" void kernel_launch(void* const* d_in, const int* in_sizes, int n_in,
                              void* d_out, int out_size)
{
    const float* cont_p = (const float*)d_in[0];
    const float* cont_c = (const float*)d_in[1];
    const int*   cat_p  = (const int*)d_in[2];
    const int*   cat_c  = (const int*)d_in[3];
    const int*   lengths= (const int*)d_in[4];
    const float* w_p1   = (const float*)d_in[5];
    const float* b_p1   = (const float*)d_in[6];
    const float* w_p2   = (const float*)d_in[7];
    const float* b_p2   = (const float*)d_in[8];
    const float* w_c1   = (const float*)d_in[9];
    const float* b_c1   = (const float*)d_in[10];
    const float* w_c2   = (const float*)d_in[11];
    const float* b_c2   = (const float*)d_in[12];
    const float* eg     = (const float*)d_in[13];
    const float* ek     = (const float*)d_in[14];
    const float* epr    = (const float*)d_in[15];
    const float* ejob   = (const float*)d_in[16];
    const float* erep   = (const float*)d_in[17];
    const float* epl    = (const float*)d_in[18];
    const float* eadd   = (const float*)d_in[19];
    const float* w_fc1  = (const float*)d_in[20];
    const float* b_fc1  = (const float*)d_in[21];
    const float* w_fc2  = (const float*)d_in[22];
    const float* b_fc2  = (const float*)d_in[23];
    float* out = (float*)d_out;

    pool_kernel<<<NB, 256>>>(cont_p, cont_c, cat_p, cat_c, lengths,
                             w_p1, b_p1, w_p2, b_p2, w_c1, b_c1, w_c2, b_c2,
                             eg, ek, epr, ejob, erep, epl, eadd);
    head_kernel<<<128, 256>>>(w_fc1, b_fc1, w_fc2, b_fc2, out);
}